// round 13
// baseline (speedup 1.0000x reference)
#include <cuda_runtime.h>
#include <cuda_fp16.h>
#include <math.h>
#include <stdint.h>

#define BB 8
#define D 768
#define NH 12
#define DH 64
#define HW 1024
#define G 5
#define S 1029           // G + HW
#define M_TOT (BB * S)   // 8232
#define SPAD 1088        // keys padded to 17*64

// ---------------- scratch (static device globals) -------------------------------
__device__ float    g_xwt  [(size_t)M_TOT * D];          // natural fp32 (residual)
__device__ __half   g_xwt16[(size_t)M_TOT * D];          // fp16 (QKV GEMM input)
__device__ uint32_t g_qk16 [(size_t)M_TOT * D];          // Q,K half2 words [row][768w]
__device__ __half   g_vt   [(size_t)BB * NH * DH * SPAD];// V transposed [b,h,dh,key]
__device__ __half   g_o    [(size_t)M_TOT * D];          // fp16 (out_proj input)
__device__ float    g_y    [(size_t)M_TOT * D];          // natural fp32
__device__ __half   g_z16  [(size_t)M_TOT * D];          // fp16 (FFN1 input)
__device__ __half   g_h16  [(size_t)M_TOT * 4 * D];      // fp16 (FFN2 input)
__device__ float    g_y2   [(size_t)M_TOT * D];          // natural fp32

// fp16 weights, half2-packed along K (uint32 words)
__device__ uint32_t g_wqkv16[3 * D * D / 2];
__device__ uint32_t g_wout16[D * D / 2];
__device__ uint32_t g_w116  [4 * D * D / 2];
__device__ uint32_t g_w216  [4 * D * D / 2];

__device__ __forceinline__ uint32_t packh2(float a, float b) {
    __half2 h = __floats2half2_rn(a, b);
    return *(uint32_t*)&h;
}
__device__ __forceinline__ void cp_async16(uint32_t dst_smem, const void* src, int src_bytes) {
    asm volatile("cp.async.cg.shared.global [%0], [%1], 16, %2;"
                 :: "r"(dst_smem), "l"(src), "r"(src_bytes));
}
__device__ __forceinline__ void cp_commit() { asm volatile("cp.async.commit_group;"); }
template<int N>
__device__ __forceinline__ void cp_wait() { asm volatile("cp.async.wait_group %0;" :: "n"(N)); }

__device__ __forceinline__ void mma_f16(float* c, const uint32_t* a, const uint32_t* b) {
    asm volatile(
        "mma.sync.aligned.m16n8k16.row.col.f32.f16.f16.f32 "
        "{%0,%1,%2,%3}, {%4,%5,%6,%7}, {%8,%9}, {%0,%1,%2,%3};"
        : "+f"(c[0]), "+f"(c[1]), "+f"(c[2]), "+f"(c[3])
        : "r"(a[0]), "r"(a[1]), "r"(a[2]), "r"(a[3]), "r"(b[0]), "r"(b[1]));
}
__device__ __forceinline__ void ldsm_x4(uint32_t* r, uint32_t addr) {
    asm volatile("ldmatrix.sync.aligned.m8n8.x4.shared.b16 {%0,%1,%2,%3}, [%4];"
                 : "=r"(r[0]), "=r"(r[1]), "=r"(r[2]), "=r"(r[3]) : "r"(addr));
}

// ---------------- weight conversion (fp32 -> fp16 half2 words) --------------------
__global__ void __launch_bounds__(256) convert_weights_kernel(
    const float* __restrict__ wqkv, const float* __restrict__ wout,
    const float* __restrict__ w1, const float* __restrict__ w2)
{
    int i = blockIdx.x * 256 + threadIdx.x;
    if (i < 3 * D * D / 2) g_wqkv16[i] = packh2(wqkv[2 * i], wqkv[2 * i + 1]);
    if (i < D * D / 2)     g_wout16[i] = packh2(wout[2 * i], wout[2 * i + 1]);
    if (i < 4 * D * D / 2) {
        g_w116[i] = packh2(w1[2 * i], w1[2 * i + 1]);
        g_w216[i] = packh2(w2[2 * i], w2[2 * i + 1]);
    }
}

// ---------------- block reduce over 256 threads ----------------------------------
__device__ __forceinline__ void block_reduce2(float& a, float& b2) {
    #pragma unroll
    for (int o = 16; o > 0; o >>= 1) {
        a  += __shfl_down_sync(0xFFFFFFFFu, a, o);
        b2 += __shfl_down_sync(0xFFFFFFFFu, b2, o);
    }
    __shared__ float sa[8], sb[8];
    int w = threadIdx.x >> 5, l = threadIdx.x & 31;
    if (l == 0) { sa[w] = a; sb[w] = b2; }
    __syncthreads();
    if (threadIdx.x < 8) {
        a = sa[threadIdx.x]; b2 = sb[threadIdx.x];
        #pragma unroll
        for (int o = 4; o > 0; o >>= 1) {
            a  += __shfl_down_sync(0xFFu, a, o);
            b2 += __shfl_down_sync(0xFFu, b2, o);
        }
        if (threadIdx.x == 0) { sa[0] = a; sb[0] = b2; }
    }
    __syncthreads();
    a = sa[0]; b2 = sb[0];
}

// ---------------- build feature rows: coalesced transpose + LN1 ------------------
#define BF_STRIDE 769
#define BUILD_SMEM (32 * BF_STRIDE * 4)

__global__ void __launch_bounds__(256) build_feat_kernel(
    const float* __restrict__ x,
    const float* __restrict__ gs, const float* __restrict__ gb)
{
    extern __shared__ float ts[];
    __shared__ float smean[32], srstd[32];
    int pt = blockIdx.x, b = blockIdx.y;
    int tid = threadIdx.x;
    int p0 = pt * 32;

    #pragma unroll 8
    for (int i = 0; i < 96; i++) {
        int e = i * 256 + tid;
        int k = e >> 5, p = e & 31;
        ts[p * BF_STRIDE + k] = x[((size_t)b * D + k) * HW + p0 + p];
    }
    __syncthreads();

    {
        int r = tid >> 3, sub = tid & 7;
        float s = 0.f, s2 = 0.f;
        #pragma unroll 8
        for (int j = 0; j < 96; j++) {
            float v = ts[r * BF_STRIDE + sub + 8 * j];
            s += v; s2 += v * v;
        }
        #pragma unroll
        for (int o = 4; o > 0; o >>= 1) {
            s  += __shfl_xor_sync(0xFFFFFFFFu, s, o);
            s2 += __shfl_xor_sync(0xFFFFFFFFu, s2, o);
        }
        if (sub == 0) {
            float mean = s * (1.0f / D);
            float var  = s2 * (1.0f / D) - mean * mean;
            smean[r] = mean;
            srstd[r] = rsqrtf(var + 1e-5f);
        }
    }
    __syncthreads();

    #pragma unroll 8
    for (int i = 0; i < 96; i++) {
        int p = i / 3;
        int k = (i % 3) * 256 + tid;
        float v = (ts[p * BF_STRIDE + k] - smean[p]) * srstd[p] * gs[k] + gb[k];
        size_t row = (size_t)(b * S + G + p0 + p);
        g_xwt  [row * D + k] = v;
        g_xwt16[row * D + k] = __float2half_rn(v);
    }
}

// ---------------- build token rows (ctx + registers + PE + LN1) ------------------
__global__ void __launch_bounds__(256) build_tok_kernel(
    const float* __restrict__ ctx, const float* __restrict__ regs,
    const float* __restrict__ gs, const float* __restrict__ gb)
{
    int blk = blockIdx.x;
    int b = blk / G, sIdx = blk % G;
    int tid = threadIdx.x;

    float vals[3];
    float s = 0.f, s2 = 0.f;
    #pragma unroll
    for (int i = 0; i < 3; i++) {
        int k = tid + i * 256;
        float base = (sIdx == 0) ? ctx[k] : regs[(sIdx - 1) * D + k];
        float expo = (float)(2 * (k / 2)) / (float)D;
        float denom = powf(10000.0f, expo);
        float angle = (float)sIdx / denom;
        float pe = (k & 1) ? cosf(angle) : sinf(angle);
        float v = base + pe;
        vals[i] = v;
        s += v; s2 += v * v;
    }
    block_reduce2(s, s2);
    float mean = s * (1.0f / D);
    float var  = s2 * (1.0f / D) - mean * mean;
    float rstd = rsqrtf(var + 1e-5f);
    size_t row = (size_t)(b * S + sIdx);
    #pragma unroll
    for (int i = 0; i < 3; i++) {
        int k = tid + i * 256;
        float v = (vals[i] - mean) * rstd * gs[k] + gb[k];
        g_xwt  [row * D + k] = v;
        g_xwt16[row * D + k] = __float2half_rn(v);
    }
}

// ---------------- LN2 (writes fp16) ------------------------------------------------
__global__ void __launch_bounds__(256) ln_kernel(
    const float* __restrict__ in, const float* __restrict__ gs,
    const float* __restrict__ gb, __half* __restrict__ out)
{
    int row = blockIdx.x;
    const float* p = in + (size_t)row * D;
    int tid = threadIdx.x;
    float vals[3];
    float s = 0.f, s2 = 0.f;
    #pragma unroll
    for (int i = 0; i < 3; i++) {
        float v = p[tid + i * 256];
        vals[i] = v; s += v; s2 += v * v;
    }
    block_reduce2(s, s2);
    float mean = s * (1.0f / D);
    float var  = s2 * (1.0f / D) - mean * mean;
    float rstd = rsqrtf(var + 1e-5f);
    #pragma unroll
    for (int i = 0; i < 3; i++) {
        int k = tid + i * 256;
        out[(size_t)row * D + k] =
            __float2half_rn((vals[i] - mean) * rstd * gs[k] + gb[k]);
    }
}

// ---------------- FP16 GEMM: m16n8k16 + ldmatrix fragments, 3-stage --------------
// OUTMODE: 0=f32(+resid), 2=f16 packed, 3=QKV split (Q*0.125,K -> g_qk16; V^T -> g_vt)
#define ASTH 20
#define BUFH (128 * ASTH)
#define GEMMH_SMEM (3 * 2 * BUFH * 4)

template<bool GELU, bool RESID, int OUTMODE>
__global__ void __launch_bounds__(256, 2) gemm_f16(
    const uint32_t* __restrict__ A, const uint32_t* __restrict__ W,
    const float* __restrict__ bias, const float* __restrict__ Rz,
    void* __restrict__ C, int Mm, int Nn, int Kk)
{
    extern __shared__ uint32_t smu[];

    int m0 = blockIdx.y * 128, n0 = blockIdx.x * 128;
    int tid = threadIdx.x;
    int warp = tid >> 5, lane = tid & 31;
    int g = lane >> 2, t = lane & 3;
    int wm = warp >> 2, wn = warp & 3;

    float acc[4][4][4];
    #pragma unroll
    for (int i = 0; i < 4; i++)
        #pragma unroll
        for (int j = 0; j < 4; j++)
            #pragma unroll
            for (int c = 0; c < 4; c++) acc[i][j][c] = 0.f;

    uint32_t smem_base = (uint32_t)__cvta_generic_to_shared(smu);
    const int KkW = Kk >> 1;
    const int ntiles = Kk >> 5;

    // ldmatrix per-lane row/col offsets (words)
    int lrow = (lane & 7) + ((lane & 8) ? 8 : 0);   // row within 16-row fragment
    int lcol = (lane & 16) ? 4 : 0;                 // k-half (words)
    int aOff = (wm * 64 + lrow) * ASTH + lcol;      // + mt*16*ASTH + s*8
    int bOff = (wn * 32 + lrow) * ASTH + lcol;      // + pair*16*ASTH + s*8

    auto load_stage = [&](int it, int stage) {
        int ktw = it * 16;
        #pragma unroll
        for (int i = 0; i < 2; i++) {
            int idx = tid + i * 256;
            int r = idx >> 2, c = (idx & 3) * 4;
            uint32_t dstA = smem_base + (stage * 2 * BUFH + r * ASTH + c) * 4;
            cp_async16(dstA, &A[(size_t)(m0 + r) * KkW + ktw + c],
                       (m0 + r < Mm) ? 16 : 0);
            uint32_t dstB = smem_base + (stage * 2 * BUFH + BUFH + r * ASTH + c) * 4;
            cp_async16(dstB, &W[(size_t)(n0 + r) * KkW + ktw + c], 16);
        }
        cp_commit();
    };

    load_stage(0, 0);
    load_stage(1, 1);

    for (int it = 0; it < ntiles; it++) {
        if (it + 1 < ntiles) cp_wait<1>(); else cp_wait<0>();
        __syncthreads();
        if (it + 2 < ntiles) {
            int st = it + 2; st -= (st / 3) * 3;
            load_stage(it + 2, st);
        }

        int cs = it - (it / 3) * 3;
        uint32_t aBase = smem_base + (cs * 2 * BUFH + aOff) * 4;
        uint32_t bBase = smem_base + (cs * 2 * BUFH + BUFH + bOff) * 4;

        #pragma unroll
        for (int s = 0; s < 2; s++) {
            uint32_t af[4][4], bf[4][2];
            #pragma unroll
            for (int mt = 0; mt < 4; mt++)
                ldsm_x4(af[mt], aBase + (mt * 16 * ASTH + s * 8) * 4);
            #pragma unroll
            for (int pr = 0; pr < 2; pr++) {
                uint32_t r[4];
                ldsm_x4(r, bBase + (pr * 16 * ASTH + s * 8) * 4);
                bf[pr * 2 + 0][0] = r[0]; bf[pr * 2 + 1][0] = r[1];
                bf[pr * 2 + 0][1] = r[2]; bf[pr * 2 + 1][1] = r[3];
            }
            #pragma unroll
            for (int mt = 0; mt < 4; mt++)
                #pragma unroll
                for (int nt = 0; nt < 4; nt++)
                    mma_f16(acc[mt][nt], af[mt], bf[nt]);
        }
        __syncthreads();   // pacing barrier — empirically load-bearing (r6 lesson)
    }

    // ---- epilogue ----
    #pragma unroll
    for (int mt = 0; mt < 4; mt++) {
        #pragma unroll
        for (int nt = 0; nt < 4; nt++) {
            int n = n0 + wn * 32 + nt * 8 + t * 2;
            float b0 = bias[n], b1 = bias[n + 1];
            #pragma unroll
            for (int half = 0; half < 2; half++) {
                int m = m0 + wm * 64 + mt * 16 + g + half * 8;
                if (m >= Mm) continue;
                float v0 = acc[mt][nt][half * 2 + 0] + b0;
                float v1 = acc[mt][nt][half * 2 + 1] + b1;
                if (GELU) {
                    v0 = 0.5f * v0 * (1.0f + erff(v0 * 0.70710678118654752f));
                    v1 = 0.5f * v1 * (1.0f + erff(v1 * 0.70710678118654752f));
                }
                if (RESID) {
                    float2 r = *(const float2*)&Rz[(size_t)m * Nn + n];
                    v0 += r.x; v1 += r.y;
                }
                if (OUTMODE == 3) {
                    if (n < 2 * D) {
                        float sc = (n < D) ? 0.125f : 1.0f;   // fold 1/sqrt(dh) into Q
                        g_qk16[(size_t)m * D + (n >> 1)] = packh2(v0 * sc, v1 * sc);
                    } else {
                        int dhg = n - 2 * D;
                        int h = dhg >> 6, dh = dhg & 63;
                        int bb = m / S, sIdx = m - bb * S;
                        __half* vt = g_vt + ((size_t)(bb * NH + h) * DH) * SPAD;
                        vt[(size_t)dh * SPAD + sIdx]       = __float2half_rn(v0);
                        vt[(size_t)(dh + 1) * SPAD + sIdx] = __float2half_rn(v1);
                    }
                } else if (OUTMODE == 2) {
                    ((uint32_t*)C)[(size_t)m * (Nn >> 1) + (n >> 1)] = packh2(v0, v1);
                } else {
                    *(float2*)&((float*)C)[(size_t)m * Nn + n] = make_float2(v0, v1);
                }
            }
        }
    }
}

// ---------------- flash attention v3: full fp16 m16n8k16 (r12 verbatim) ----------
#define KSTH16 36
#define KVW (64 * KSTH16)
#define ATTN16_SMEM ((4 * KVW + 128 * KSTH16) * 4)

__global__ void __launch_bounds__(128, 3) attn_f16_kernel()
{
    extern __shared__ uint32_t asmu[];
    uint32_t* Pw = asmu + 4 * KVW;

    int qt = blockIdx.x, h = blockIdx.y, b = blockIdx.z;
    int tid = threadIdx.x;
    int warp = tid >> 5, lane = tid & 31;
    int g = lane >> 2, t = lane & 3;

    uint32_t smem_base = (uint32_t)__cvta_generic_to_shared(asmu);
    int rbase = qt * 128 + warp * 16 + g;

    uint32_t qf[2][4][4];
    #pragma unroll
    for (int mg = 0; mg < 2; mg++) {
        int r0 = rbase + mg * 64, r1 = r0 + 8;
        bool v0 = r0 < S, v1 = r1 < S;
        const uint32_t* q0 = g_qk16 + (size_t)(b * S + (v0 ? r0 : 0)) * D + h * 32;
        const uint32_t* q1 = g_qk16 + (size_t)(b * S + (v1 ? r1 : 0)) * D + h * 32;
        #pragma unroll
        for (int ks = 0; ks < 4; ks++) {
            qf[mg][ks][0] = v0 ? q0[ks * 8 + t] : 0u;
            qf[mg][ks][1] = v1 ? q1[ks * 8 + t] : 0u;
            qf[mg][ks][2] = v0 ? q0[ks * 8 + t + 4] : 0u;
            qf[mg][ks][3] = v1 ? q1[ks * 8 + t + 4] : 0u;
        }
    }

    float oacc[2][8][4];
    #pragma unroll
    for (int mg = 0; mg < 2; mg++)
        #pragma unroll
        for (int i = 0; i < 8; i++)
            #pragma unroll
            for (int c = 0; c < 4; c++) oacc[mg][i][c] = 0.f;
    float mr[2][2], lr[2][2];
    #pragma unroll
    for (int mg = 0; mg < 2; mg++) {
        mr[mg][0] = mr[mg][1] = -1e30f;
        lr[mg][0] = lr[mg][1] = 0.f;
    }

    const int NT = (S + 63) / 64;
    const uint32_t* vtw = (const uint32_t*)(g_vt + (size_t)(b * NH + h) * DH * SPAD);

    auto load_kv = [&](int kt, int st) {
        #pragma unroll
        for (int i = 0; i < 4; i++) {
            int idx = tid + i * 128;
            int r = idx >> 3, c = (idx & 7) * 4;
            int ki = kt * 64 + r;
            int bytes = (ki < S) ? 16 : 0;
            const uint32_t* ksrc = g_qk16 +
                (size_t)(b * S + (ki < S ? ki : 0)) * D + (D >> 1) + h * 32 + c;
            cp_async16(smem_base + (st * 2 * KVW + r * KSTH16 + c) * 4, ksrc, bytes);
            const uint32_t* vsrc = vtw + (size_t)r * (SPAD >> 1) + kt * 32 + c;
            cp_async16(smem_base + (st * 2 * KVW + KVW + r * KSTH16 + c) * 4, vsrc, 16);
        }
        cp_commit();
    };

    load_kv(0, 0);

    for (int kt = 0; kt < NT; kt++) {
        if (kt + 1 < NT) { load_kv(kt + 1, (kt + 1) & 1); cp_wait<1>(); }
        else             { cp_wait<0>(); }
        __syncthreads();

        const uint32_t* Ks = asmu + (kt & 1) * 2 * KVW;
        const uint32_t* Vs = Ks + KVW;

        float sacc[2][8][4];
        #pragma unroll
        for (int mg = 0; mg < 2; mg++)
            #pragma unroll
            for (int nt = 0; nt < 8; nt++)
                #pragma unroll
                for (int c = 0; c < 4; c++) sacc[mg][nt][c] = 0.f;

        #pragma unroll
        for (int ks = 0; ks < 4; ks++) {
            #pragma unroll
            for (int nt = 0; nt < 8; nt++) {
                uint32_t bf[2];
                bf[0] = Ks[(nt * 8 + g) * KSTH16 + ks * 8 + t];
                bf[1] = Ks[(nt * 8 + g) * KSTH16 + ks * 8 + t + 4];
                mma_f16(sacc[0][nt], qf[0][ks], bf);
                mma_f16(sacc[1][nt], qf[1][ks], bf);
            }
        }

        #pragma unroll
        for (int mg = 0; mg < 2; mg++) {
            int r0 = rbase + mg * 64, r1 = r0 + 8;
            bool feat0 = r0 >= G, feat1 = r1 >= G;
            float mx0 = -1e30f, mx1 = -1e30f;
            #pragma unroll
            for (int nt = 0; nt < 8; nt++) {
                #pragma unroll
                for (int c = 0; c < 4; c++) {
                    int col = kt * 64 + nt * 8 + 2 * t + (c & 1);
                    bool bad = (col >= S) || ((c < 2 ? feat0 : feat1) && col < G);
                    if (bad) sacc[mg][nt][c] = -1e30f;
                }
                mx0 = fmaxf(mx0, fmaxf(sacc[mg][nt][0], sacc[mg][nt][1]));
                mx1 = fmaxf(mx1, fmaxf(sacc[mg][nt][2], sacc[mg][nt][3]));
            }
            mx0 = fmaxf(mx0, __shfl_xor_sync(0xFFFFFFFFu, mx0, 1));
            mx0 = fmaxf(mx0, __shfl_xor_sync(0xFFFFFFFFu, mx0, 2));
            mx1 = fmaxf(mx1, __shfl_xor_sync(0xFFFFFFFFu, mx1, 1));
            mx1 = fmaxf(mx1, __shfl_xor_sync(0xFFFFFFFFu, mx1, 2));

            float mn0 = fmaxf(mr[mg][0], mx0), mn1 = fmaxf(mr[mg][1], mx1);
            float sc0 = __expf(mr[mg][0] - mn0), sc1 = __expf(mr[mg][1] - mn1);
            mr[mg][0] = mn0; mr[mg][1] = mn1;

            float ls0 = 0.f, ls1 = 0.f;
            int prow0 = (mg * 64 + warp * 16 + g) * KSTH16;
            int prow1 = prow0 + 8 * KSTH16;
            #pragma unroll
            for (int nt = 0; nt < 8; nt++) {
                float p0 = __expf(sacc[mg][nt][0] - mn0);
                float p1 = __expf(sacc[mg][nt][1] - mn0);
                float p2 = __expf(sacc[mg][nt][2] - mn1);
                float p3 = __expf(sacc[mg][nt][3] - mn1);
                ls0 += p0 + p1; ls1 += p2 + p3;
                Pw[prow0 + nt * 4 + t] = packh2(p0, p1);
                Pw[prow1 + nt * 4 + t] = packh2(p2, p3);
                #pragma unroll
                for (int c = 0; c < 4; c++)
                    oacc[mg][nt][c] *= (c < 2) ? sc0 : sc1;
            }
            ls0 += __shfl_xor_sync(0xFFFFFFFFu, ls0, 1);
            ls0 += __shfl_xor_sync(0xFFFFFFFFu, ls0, 2);
            ls1 += __shfl_xor_sync(0xFFFFFFFFu, ls1, 1);
            ls1 += __shfl_xor_sync(0xFFFFFFFFu, ls1, 2);
            lr[mg][0] = lr[mg][0] * sc0 + ls0;
            lr[mg][1] = lr[mg][1] * sc1 + ls1;
        }
        __syncwarp();

        #pragma unroll
        for (int ks = 0; ks < 4; ks++) {
            uint32_t vf[8][2];
            #pragma unroll
            for (int nt = 0; nt < 8; nt++) {
                vf[nt][0] = Vs[(nt * 8 + g) * KSTH16 + ks * 8 + t];
                vf[nt][1] = Vs[(nt * 8 + g) * KSTH16 + ks * 8 + t + 4];
            }
            #pragma unroll
            for (int mg = 0; mg < 2; mg++) {
                int prow0 = (mg * 64 + warp * 16 + g) * KSTH16;
                int prow1 = prow0 + 8 * KSTH16;
                uint32_t pf[4];
                pf[0] = Pw[prow0 + ks * 8 + t];
                pf[1] = Pw[prow1 + ks * 8 + t];
                pf[2] = Pw[prow0 + ks * 8 + t + 4];
                pf[3] = Pw[prow1 + ks * 8 + t + 4];
                #pragma unroll
                for (int nt = 0; nt < 8; nt++)
                    mma_f16(oacc[mg][nt], pf, vf[nt]);
            }
        }
        __syncthreads();
    }

    #pragma unroll
    for (int mg = 0; mg < 2; mg++) {
        int r0 = rbase + mg * 64, r1 = r0 + 8;
        bool v0 = r0 < S, v1 = r1 < S;
        float inv0 = 1.0f / lr[mg][0], inv1 = 1.0f / lr[mg][1];
        uint32_t* o0 = (uint32_t*)(g_o + (size_t)(b * S + (v0 ? r0 : 0)) * D + h * DH);
        uint32_t* o1 = (uint32_t*)(g_o + (size_t)(b * S + (v1 ? r1 : 0)) * D + h * DH);
        #pragma unroll
        for (int nt = 0; nt < 8; nt++) {
            int wbase = nt * 4 + t;
            if (v0) o0[wbase] = packh2(oacc[mg][nt][0] * inv0, oacc[mg][nt][1] * inv0);
            if (v1) o1[wbase] = packh2(oacc[mg][nt][2] * inv1, oacc[mg][nt][3] * inv1);
        }
    }
}

// ---------------- scatter: feature (smem transpose) + tokens ---------------------
__global__ void __launch_bounds__(256) scatter_feat_kernel(float* __restrict__ out)
{
    __shared__ float ts[32 * 33];
    int pt = blockIdx.x, kt = blockIdx.y, b = blockIdx.z;
    int tid = threadIdx.x;
    int p0 = pt * 32, k0 = kt * 32;
    #pragma unroll
    for (int i = 0; i < 4; i++) {
        int e = i * 256 + tid;
        int p = e >> 5, k = e & 31;
        ts[p * 33 + k] = g_y2[((size_t)(b * S + G + p0 + p)) * D + k0 + k];
    }
    __syncthreads();
    #pragma unroll
    for (int i = 0; i < 4; i++) {
        int e = i * 256 + tid;
        int k = e >> 5, p = e & 31;
        out[((size_t)b * D + k0 + k) * HW + p0 + p] = ts[p * 33 + k];
    }
}

__global__ void __launch_bounds__(256) scatter_tok_kernel(float* __restrict__ out)
{
    const int FEAT = BB * D * HW;
    const int CTX  = BB * D;
    int r = blockIdx.x;
    int b = r / G, s = r % G;
    int tid = threadIdx.x;
    #pragma unroll
    for (int i = 0; i < 3; i++) {
        int k = tid + i * 256;
        float v = g_y2[((size_t)(b * S + s)) * D + k];
        if (s == 0) out[FEAT + b * D + k] = v;
        else        out[FEAT + CTX + ((size_t)b * 4 + (s - 1)) * D + k] = v;
    }
}

// ---------------- host launcher ---------------------------------------------------
extern "C" void kernel_launch(void* const* d_in, const int* in_sizes, int n_in,
                              void* d_out, int out_size)
{
    const float* x    = (const float*)d_in[0];
    const float* ctx  = (const float*)d_in[1];
    const float* regs = (const float*)d_in[2];
    const float* wqkv = (const float*)d_in[3];
    const float* bqkv = (const float*)d_in[4];
    const float* wout = (const float*)d_in[5];
    const float* bout = (const float*)d_in[6];
    const float* ln1s = (const float*)d_in[7];
    const float* ln1b = (const float*)d_in[8];
    const float* ln2s = (const float*)d_in[9];
    const float* ln2b = (const float*)d_in[10];
    const float* w1   = (const float*)d_in[11];
    const float* b1   = (const float*)d_in[12];
    const float* w2   = (const float*)d_in[13];
    const float* b2   = (const float*)d_in[14];
    float* out = (float*)d_out;
    (void)in_sizes; (void)n_in; (void)out_size;

    void *xwt16, *o, *z16, *h16;
    void *wqkv16, *wout16, *w116, *w216;
    float *xwt, *y, *y2;
    cudaGetSymbolAddress((void**)&xwt,    g_xwt);
    cudaGetSymbolAddress(&xwt16,  g_xwt16);
    cudaGetSymbolAddress(&o,      g_o);
    cudaGetSymbolAddress((void**)&y,      g_y);
    cudaGetSymbolAddress(&z16,    g_z16);
    cudaGetSymbolAddress(&h16,    g_h16);
    cudaGetSymbolAddress((void**)&y2,     g_y2);
    cudaGetSymbolAddress(&wqkv16, g_wqkv16);
    cudaGetSymbolAddress(&wout16, g_wout16);
    cudaGetSymbolAddress(&w116,   g_w116);
    cudaGetSymbolAddress(&w216,   g_w216);

    cudaFuncSetAttribute(gemm_f16<false, false, 3>,
        cudaFuncAttributeMaxDynamicSharedMemorySize, GEMMH_SMEM);
    cudaFuncSetAttribute(gemm_f16<false, true, 0>,
        cudaFuncAttributeMaxDynamicSharedMemorySize, GEMMH_SMEM);
    cudaFuncSetAttribute(gemm_f16<true, false, 2>,
        cudaFuncAttributeMaxDynamicSharedMemorySize, GEMMH_SMEM);
    cudaFuncSetAttribute(attn_f16_kernel,
        cudaFuncAttributeMaxDynamicSharedMemorySize, ATTN16_SMEM);
    cudaFuncSetAttribute(build_feat_kernel,
        cudaFuncAttributeMaxDynamicSharedMemorySize, BUILD_SMEM);

    const int M = M_TOT;
    const int MG = (M + 127) / 128;            // 65

    convert_weights_kernel<<<(4 * D * D / 2 + 255) / 256, 256>>>(wqkv, wout, w1, w2);

    build_feat_kernel<<<dim3(HW / 32, BB), 256, BUILD_SMEM>>>(x, ln1s, ln1b);
    build_tok_kernel<<<BB * G, 256>>>(ctx, regs, ln1s, ln1b);

    gemm_f16<false, false, 3><<<dim3(3 * D / 128, MG), 256, GEMMH_SMEM>>>(
        (const uint32_t*)xwt16, (const uint32_t*)wqkv16, bqkv, nullptr,
        nullptr, M, 3 * D, D);

    attn_f16_kernel<<<dim3((S + 127) / 128, NH, BB), 128, ATTN16_SMEM>>>();

    gemm_f16<false, true, 0><<<dim3(D / 128, MG), 256, GEMMH_SMEM>>>(
        (const uint32_t*)o, (const uint32_t*)wout16, bout, xwt,
        y, M, D, D);

    ln_kernel<<<M, 256>>>(y, ln2s, ln2b, (__half*)z16);

    gemm_f16<true, false, 2><<<dim3(4 * D / 128, MG), 256, GEMMH_SMEM>>>(
        (const uint32_t*)z16, (const uint32_t*)w116, b1, nullptr,
        h16, M, 4 * D, D);

    gemm_f16<false, true, 0><<<dim3(D / 128, MG), 256, GEMMH_SMEM>>>(
        (const uint32_t*)h16, (const uint32_t*)w216, b2, y,
        y2, M, D, 4 * D);

    scatter_feat_kernel<<<dim3(HW / 32, D / 32, BB), 256>>>(out);
    scatter_tok_kernel<<<BB * G, 256>>>(out);
}

// round 14
// speedup vs baseline: 1.1328x; 1.1328x over previous
#include <cuda_runtime.h>
#include <cuda_fp16.h>
#include <math.h>
#include <stdint.h>

#define BB 8
#define D 768
#define NH 12
#define DH 64
#define HW 1024
#define G 5
#define S 1029           // G + HW
#define M_TOT (BB * S)   // 8232
#define SPAD 1088        // keys padded to 17*64

// ---------------- scratch (static device globals) -------------------------------
__device__ float    g_xwt  [(size_t)M_TOT * D];          // natural fp32 (residual)
__device__ __half   g_xwt16[(size_t)M_TOT * D];          // fp16 (QKV GEMM input)
__device__ uint32_t g_qk16 [(size_t)M_TOT * D];          // Q,K half2 words [row][768w]
__device__ __half   g_vt   [(size_t)BB * NH * DH * SPAD];// V transposed [b,h,dh,key]
__device__ __half   g_o    [(size_t)M_TOT * D];          // fp16 (out_proj input)
__device__ float    g_y    [(size_t)M_TOT * D];          // natural fp32
__device__ __half   g_z16  [(size_t)M_TOT * D];          // fp16 (FFN1 input)
__device__ __half   g_h16  [(size_t)M_TOT * 4 * D];      // fp16 (FFN2 input)
__device__ float    g_y2   [(size_t)M_TOT * D];          // natural fp32

// fp16 weights, half2-packed along K (uint32 words)
__device__ uint32_t g_wqkv16[3 * D * D / 2];
__device__ uint32_t g_wout16[D * D / 2];
__device__ uint32_t g_w116  [4 * D * D / 2];
__device__ uint32_t g_w216  [4 * D * D / 2];

__device__ __forceinline__ uint32_t packh2(float a, float b) {
    __half2 h = __floats2half2_rn(a, b);
    return *(uint32_t*)&h;
}
__device__ __forceinline__ void cp_async16(uint32_t dst_smem, const void* src, int src_bytes) {
    asm volatile("cp.async.cg.shared.global [%0], [%1], 16, %2;"
                 :: "r"(dst_smem), "l"(src), "r"(src_bytes));
}
__device__ __forceinline__ void cp_commit() { asm volatile("cp.async.commit_group;"); }
template<int N>
__device__ __forceinline__ void cp_wait() { asm volatile("cp.async.wait_group %0;" :: "n"(N)); }

__device__ __forceinline__ void mma_f16(float* c, const uint32_t* a, const uint32_t* b) {
    asm volatile(
        "mma.sync.aligned.m16n8k16.row.col.f32.f16.f16.f32 "
        "{%0,%1,%2,%3}, {%4,%5,%6,%7}, {%8,%9}, {%0,%1,%2,%3};"
        : "+f"(c[0]), "+f"(c[1]), "+f"(c[2]), "+f"(c[3])
        : "r"(a[0]), "r"(a[1]), "r"(a[2]), "r"(a[3]), "r"(b[0]), "r"(b[1]));
}

// ---------------- weight conversion (fp32 -> fp16 half2 words) --------------------
__global__ void __launch_bounds__(256) convert_weights_kernel(
    const float* __restrict__ wqkv, const float* __restrict__ wout,
    const float* __restrict__ w1, const float* __restrict__ w2)
{
    int i = blockIdx.x * 256 + threadIdx.x;
    if (i < 3 * D * D / 2) g_wqkv16[i] = packh2(wqkv[2 * i], wqkv[2 * i + 1]);
    if (i < D * D / 2)     g_wout16[i] = packh2(wout[2 * i], wout[2 * i + 1]);
    if (i < 4 * D * D / 2) {
        g_w116[i] = packh2(w1[2 * i], w1[2 * i + 1]);
        g_w216[i] = packh2(w2[2 * i], w2[2 * i + 1]);
    }
}

// ---------------- block reduce over 256 threads ----------------------------------
__device__ __forceinline__ void block_reduce2(float& a, float& b2) {
    #pragma unroll
    for (int o = 16; o > 0; o >>= 1) {
        a  += __shfl_down_sync(0xFFFFFFFFu, a, o);
        b2 += __shfl_down_sync(0xFFFFFFFFu, b2, o);
    }
    __shared__ float sa[8], sb[8];
    int w = threadIdx.x >> 5, l = threadIdx.x & 31;
    if (l == 0) { sa[w] = a; sb[w] = b2; }
    __syncthreads();
    if (threadIdx.x < 8) {
        a = sa[threadIdx.x]; b2 = sb[threadIdx.x];
        #pragma unroll
        for (int o = 4; o > 0; o >>= 1) {
            a  += __shfl_down_sync(0xFFu, a, o);
            b2 += __shfl_down_sync(0xFFu, b2, o);
        }
        if (threadIdx.x == 0) { sa[0] = a; sb[0] = b2; }
    }
    __syncthreads();
    a = sa[0]; b2 = sb[0];
}

// ---------------- build feature rows: coalesced transpose + LN1 ------------------
#define BF_STRIDE 769
#define BUILD_SMEM (32 * BF_STRIDE * 4)

__global__ void __launch_bounds__(256) build_feat_kernel(
    const float* __restrict__ x,
    const float* __restrict__ gs, const float* __restrict__ gb)
{
    extern __shared__ float ts[];
    __shared__ float smean[32], srstd[32];
    int pt = blockIdx.x, b = blockIdx.y;
    int tid = threadIdx.x;
    int p0 = pt * 32;

    #pragma unroll 8
    for (int i = 0; i < 96; i++) {
        int e = i * 256 + tid;
        int k = e >> 5, p = e & 31;
        ts[p * BF_STRIDE + k] = x[((size_t)b * D + k) * HW + p0 + p];
    }
    __syncthreads();

    {
        int r = tid >> 3, sub = tid & 7;
        float s = 0.f, s2 = 0.f;
        #pragma unroll 8
        for (int j = 0; j < 96; j++) {
            float v = ts[r * BF_STRIDE + sub + 8 * j];
            s += v; s2 += v * v;
        }
        #pragma unroll
        for (int o = 4; o > 0; o >>= 1) {
            s  += __shfl_xor_sync(0xFFFFFFFFu, s, o);
            s2 += __shfl_xor_sync(0xFFFFFFFFu, s2, o);
        }
        if (sub == 0) {
            float mean = s * (1.0f / D);
            float var  = s2 * (1.0f / D) - mean * mean;
            smean[r] = mean;
            srstd[r] = rsqrtf(var + 1e-5f);
        }
    }
    __syncthreads();

    #pragma unroll 8
    for (int i = 0; i < 96; i++) {
        int p = i / 3;
        int k = (i % 3) * 256 + tid;
        float v = (ts[p * BF_STRIDE + k] - smean[p]) * srstd[p] * gs[k] + gb[k];
        size_t row = (size_t)(b * S + G + p0 + p);
        g_xwt  [row * D + k] = v;
        g_xwt16[row * D + k] = __float2half_rn(v);
    }
}

// ---------------- build token rows (ctx + registers + PE + LN1) ------------------
__global__ void __launch_bounds__(256) build_tok_kernel(
    const float* __restrict__ ctx, const float* __restrict__ regs,
    const float* __restrict__ gs, const float* __restrict__ gb)
{
    int blk = blockIdx.x;
    int b = blk / G, sIdx = blk % G;
    int tid = threadIdx.x;

    float vals[3];
    float s = 0.f, s2 = 0.f;
    #pragma unroll
    for (int i = 0; i < 3; i++) {
        int k = tid + i * 256;
        float base = (sIdx == 0) ? ctx[k] : regs[(sIdx - 1) * D + k];
        float expo = (float)(2 * (k / 2)) / (float)D;
        float denom = powf(10000.0f, expo);
        float angle = (float)sIdx / denom;
        float pe = (k & 1) ? cosf(angle) : sinf(angle);
        float v = base + pe;
        vals[i] = v;
        s += v; s2 += v * v;
    }
    block_reduce2(s, s2);
    float mean = s * (1.0f / D);
    float var  = s2 * (1.0f / D) - mean * mean;
    float rstd = rsqrtf(var + 1e-5f);
    size_t row = (size_t)(b * S + sIdx);
    #pragma unroll
    for (int i = 0; i < 3; i++) {
        int k = tid + i * 256;
        float v = (vals[i] - mean) * rstd * gs[k] + gb[k];
        g_xwt  [row * D + k] = v;
        g_xwt16[row * D + k] = __float2half_rn(v);
    }
}

// ---------------- LN2 (writes fp16) ------------------------------------------------
__global__ void __launch_bounds__(256) ln_kernel(
    const float* __restrict__ in, const float* __restrict__ gs,
    const float* __restrict__ gb, __half* __restrict__ out)
{
    int row = blockIdx.x;
    const float* p = in + (size_t)row * D;
    int tid = threadIdx.x;
    float vals[3];
    float s = 0.f, s2 = 0.f;
    #pragma unroll
    for (int i = 0; i < 3; i++) {
        float v = p[tid + i * 256];
        vals[i] = v; s += v; s2 += v * v;
    }
    block_reduce2(s, s2);
    float mean = s * (1.0f / D);
    float var  = s2 * (1.0f / D) - mean * mean;
    float rstd = rsqrtf(var + 1e-5f);
    #pragma unroll
    for (int i = 0; i < 3; i++) {
        int k = tid + i * 256;
        out[(size_t)row * D + k] =
            __float2half_rn((vals[i] - mean) * rstd * gs[k] + gb[k]);
    }
}

// ---------------- FP16 GEMM: m16n8k16, KT=64, 2-stage cp.async -------------------
// OUTMODE: 0=f32(+resid), 2=f16 packed, 3=QKV split (Q*0.125,K -> g_qk16; V^T -> g_vt)
#define ASTH 36                    // 32 data words + 4 pad (banks 4g+t, conflict-free)
#define BUFH (128 * ASTH)
#define GEMMH_SMEM (2 * 2 * BUFH * 4)   // 2 stages x (A,B)

template<bool GELU, bool RESID, int OUTMODE>
__global__ void __launch_bounds__(256, 2) gemm_f16(
    const uint32_t* __restrict__ A, const uint32_t* __restrict__ W,
    const float* __restrict__ bias, const float* __restrict__ Rz,
    void* __restrict__ C, int Mm, int Nn, int Kk)
{
    extern __shared__ uint32_t smu[];

    int m0 = blockIdx.y * 128, n0 = blockIdx.x * 128;
    int tid = threadIdx.x;
    int warp = tid >> 5, lane = tid & 31;
    int g = lane >> 2, t = lane & 3;
    int wm = warp >> 2, wn = warp & 3;

    float acc[4][4][4];
    #pragma unroll
    for (int i = 0; i < 4; i++)
        #pragma unroll
        for (int j = 0; j < 4; j++)
            #pragma unroll
            for (int c = 0; c < 4; c++) acc[i][j][c] = 0.f;

    uint32_t smem_base = (uint32_t)__cvta_generic_to_shared(smu);
    const int KkW = Kk >> 1;
    const int ntiles = Kk >> 6;     // KT = 64 elements = 32 words

    auto load_stage = [&](int it, int stage) {
        int ktw = it * 32;
        #pragma unroll
        for (int i = 0; i < 4; i++) {
            int idx = tid + i * 256;           // 0..1023: 128 rows x 8 chunks
            int r = idx >> 3, c = (idx & 7) * 4;
            uint32_t dstA = smem_base + (stage * 2 * BUFH + r * ASTH + c) * 4;
            cp_async16(dstA, &A[(size_t)(m0 + r) * KkW + ktw + c],
                       (m0 + r < Mm) ? 16 : 0);
            uint32_t dstB = smem_base + (stage * 2 * BUFH + BUFH + r * ASTH + c) * 4;
            cp_async16(dstB, &W[(size_t)(n0 + r) * KkW + ktw + c], 16);
        }
        cp_commit();
    };

    load_stage(0, 0);

    for (int it = 0; it < ntiles; it++) {
        if (it + 1 < ntiles) { load_stage(it + 1, (it + 1) & 1); cp_wait<1>(); }
        else                 { cp_wait<0>(); }
        __syncthreads();

        const uint32_t* Ab = smu + (it & 1) * 2 * BUFH;
        const uint32_t* Bb = Ab + BUFH;

        #pragma unroll
        for (int s = 0; s < 4; s++) {          // four k16 steps per tile
            uint32_t af[4][4], bf[4][2];
            #pragma unroll
            for (int mt = 0; mt < 4; mt++) {
                int m = wm * 64 + mt * 16 + g;
                af[mt][0] = Ab[m * ASTH + s * 8 + t];
                af[mt][1] = Ab[(m + 8) * ASTH + s * 8 + t];
                af[mt][2] = Ab[m * ASTH + s * 8 + t + 4];
                af[mt][3] = Ab[(m + 8) * ASTH + s * 8 + t + 4];
            }
            #pragma unroll
            for (int nt = 0; nt < 4; nt++) {
                int n = wn * 32 + nt * 8 + g;
                bf[nt][0] = Bb[n * ASTH + s * 8 + t];
                bf[nt][1] = Bb[n * ASTH + s * 8 + t + 4];
            }
            #pragma unroll
            for (int mt = 0; mt < 4; mt++)
                #pragma unroll
                for (int nt = 0; nt < 4; nt++)
                    mma_f16(acc[mt][nt], af[mt], bf[nt]);
        }
        __syncthreads();   // pacing barrier — empirically load-bearing (r6 lesson)
    }

    // ---- epilogue ----
    #pragma unroll
    for (int mt = 0; mt < 4; mt++) {
        #pragma unroll
        for (int nt = 0; nt < 4; nt++) {
            int n = n0 + wn * 32 + nt * 8 + t * 2;
            float b0 = bias[n], b1 = bias[n + 1];
            #pragma unroll
            for (int half = 0; half < 2; half++) {
                int m = m0 + wm * 64 + mt * 16 + g + half * 8;
                if (m >= Mm) continue;
                float v0 = acc[mt][nt][half * 2 + 0] + b0;
                float v1 = acc[mt][nt][half * 2 + 1] + b1;
                if (GELU) {
                    v0 = 0.5f * v0 * (1.0f + erff(v0 * 0.70710678118654752f));
                    v1 = 0.5f * v1 * (1.0f + erff(v1 * 0.70710678118654752f));
                }
                if (RESID) {
                    float2 r = *(const float2*)&Rz[(size_t)m * Nn + n];
                    v0 += r.x; v1 += r.y;
                }
                if (OUTMODE == 3) {
                    if (n < 2 * D) {
                        float sc = (n < D) ? 0.125f : 1.0f;   // fold 1/sqrt(dh) into Q
                        g_qk16[(size_t)m * D + (n >> 1)] = packh2(v0 * sc, v1 * sc);
                    } else {
                        int dhg = n - 2 * D;
                        int h = dhg >> 6, dh = dhg & 63;
                        int bb = m / S, sIdx = m - bb * S;
                        __half* vt = g_vt + ((size_t)(bb * NH + h) * DH) * SPAD;
                        vt[(size_t)dh * SPAD + sIdx]       = __float2half_rn(v0);
                        vt[(size_t)(dh + 1) * SPAD + sIdx] = __float2half_rn(v1);
                    }
                } else if (OUTMODE == 2) {
                    ((uint32_t*)C)[(size_t)m * (Nn >> 1) + (n >> 1)] = packh2(v0, v1);
                } else {
                    *(float2*)&((float*)C)[(size_t)m * Nn + n] = make_float2(v0, v1);
                }
            }
        }
    }
}

// ---------------- flash attention v3: full fp16 m16n8k16 (r12 verbatim) ----------
#define KSTH16 36
#define KVW (64 * KSTH16)
#define ATTN16_SMEM ((4 * KVW + 128 * KSTH16) * 4)

__global__ void __launch_bounds__(128, 3) attn_f16_kernel()
{
    extern __shared__ uint32_t asmu[];
    uint32_t* Pw = asmu + 4 * KVW;

    int qt = blockIdx.x, h = blockIdx.y, b = blockIdx.z;
    int tid = threadIdx.x;
    int warp = tid >> 5, lane = tid & 31;
    int g = lane >> 2, t = lane & 3;

    uint32_t smem_base = (uint32_t)__cvta_generic_to_shared(asmu);
    int rbase = qt * 128 + warp * 16 + g;

    uint32_t qf[2][4][4];
    #pragma unroll
    for (int mg = 0; mg < 2; mg++) {
        int r0 = rbase + mg * 64, r1 = r0 + 8;
        bool v0 = r0 < S, v1 = r1 < S;
        const uint32_t* q0 = g_qk16 + (size_t)(b * S + (v0 ? r0 : 0)) * D + h * 32;
        const uint32_t* q1 = g_qk16 + (size_t)(b * S + (v1 ? r1 : 0)) * D + h * 32;
        #pragma unroll
        for (int ks = 0; ks < 4; ks++) {
            qf[mg][ks][0] = v0 ? q0[ks * 8 + t] : 0u;
            qf[mg][ks][1] = v1 ? q1[ks * 8 + t] : 0u;
            qf[mg][ks][2] = v0 ? q0[ks * 8 + t + 4] : 0u;
            qf[mg][ks][3] = v1 ? q1[ks * 8 + t + 4] : 0u;
        }
    }

    float oacc[2][8][4];
    #pragma unroll
    for (int mg = 0; mg < 2; mg++)
        #pragma unroll
        for (int i = 0; i < 8; i++)
            #pragma unroll
            for (int c = 0; c < 4; c++) oacc[mg][i][c] = 0.f;
    float mr[2][2], lr[2][2];
    #pragma unroll
    for (int mg = 0; mg < 2; mg++) {
        mr[mg][0] = mr[mg][1] = -1e30f;
        lr[mg][0] = lr[mg][1] = 0.f;
    }

    const int NT = (S + 63) / 64;
    const uint32_t* vtw = (const uint32_t*)(g_vt + (size_t)(b * NH + h) * DH * SPAD);

    auto load_kv = [&](int kt, int st) {
        #pragma unroll
        for (int i = 0; i < 4; i++) {
            int idx = tid + i * 128;
            int r = idx >> 3, c = (idx & 7) * 4;
            int ki = kt * 64 + r;
            int bytes = (ki < S) ? 16 : 0;
            const uint32_t* ksrc = g_qk16 +
                (size_t)(b * S + (ki < S ? ki : 0)) * D + (D >> 1) + h * 32 + c;
            cp_async16(smem_base + (st * 2 * KVW + r * KSTH16 + c) * 4, ksrc, bytes);
            const uint32_t* vsrc = vtw + (size_t)r * (SPAD >> 1) + kt * 32 + c;
            cp_async16(smem_base + (st * 2 * KVW + KVW + r * KSTH16 + c) * 4, vsrc, 16);
        }
        cp_commit();
    };

    load_kv(0, 0);

    for (int kt = 0; kt < NT; kt++) {
        if (kt + 1 < NT) { load_kv(kt + 1, (kt + 1) & 1); cp_wait<1>(); }
        else             { cp_wait<0>(); }
        __syncthreads();

        const uint32_t* Ks = asmu + (kt & 1) * 2 * KVW;
        const uint32_t* Vs = Ks + KVW;

        float sacc[2][8][4];
        #pragma unroll
        for (int mg = 0; mg < 2; mg++)
            #pragma unroll
            for (int nt = 0; nt < 8; nt++)
                #pragma unroll
                for (int c = 0; c < 4; c++) sacc[mg][nt][c] = 0.f;

        #pragma unroll
        for (int ks = 0; ks < 4; ks++) {
            #pragma unroll
            for (int nt = 0; nt < 8; nt++) {
                uint32_t bf[2];
                bf[0] = Ks[(nt * 8 + g) * KSTH16 + ks * 8 + t];
                bf[1] = Ks[(nt * 8 + g) * KSTH16 + ks * 8 + t + 4];
                mma_f16(sacc[0][nt], qf[0][ks], bf);
                mma_f16(sacc[1][nt], qf[1][ks], bf);
            }
        }

        #pragma unroll
        for (int mg = 0; mg < 2; mg++) {
            int r0 = rbase + mg * 64, r1 = r0 + 8;
            bool feat0 = r0 >= G, feat1 = r1 >= G;
            float mx0 = -1e30f, mx1 = -1e30f;
            #pragma unroll
            for (int nt = 0; nt < 8; nt++) {
                #pragma unroll
                for (int c = 0; c < 4; c++) {
                    int col = kt * 64 + nt * 8 + 2 * t + (c & 1);
                    bool bad = (col >= S) || ((c < 2 ? feat0 : feat1) && col < G);
                    if (bad) sacc[mg][nt][c] = -1e30f;
                }
                mx0 = fmaxf(mx0, fmaxf(sacc[mg][nt][0], sacc[mg][nt][1]));
                mx1 = fmaxf(mx1, fmaxf(sacc[mg][nt][2], sacc[mg][nt][3]));
            }
            mx0 = fmaxf(mx0, __shfl_xor_sync(0xFFFFFFFFu, mx0, 1));
            mx0 = fmaxf(mx0, __shfl_xor_sync(0xFFFFFFFFu, mx0, 2));
            mx1 = fmaxf(mx1, __shfl_xor_sync(0xFFFFFFFFu, mx1, 1));
            mx1 = fmaxf(mx1, __shfl_xor_sync(0xFFFFFFFFu, mx1, 2));

            float mn0 = fmaxf(mr[mg][0], mx0), mn1 = fmaxf(mr[mg][1], mx1);
            float sc0 = __expf(mr[mg][0] - mn0), sc1 = __expf(mr[mg][1] - mn1);
            mr[mg][0] = mn0; mr[mg][1] = mn1;

            float ls0 = 0.f, ls1 = 0.f;
            int prow0 = (mg * 64 + warp * 16 + g) * KSTH16;
            int prow1 = prow0 + 8 * KSTH16;
            #pragma unroll
            for (int nt = 0; nt < 8; nt++) {
                float p0 = __expf(sacc[mg][nt][0] - mn0);
                float p1 = __expf(sacc[mg][nt][1] - mn0);
                float p2 = __expf(sacc[mg][nt][2] - mn1);
                float p3 = __expf(sacc[mg][nt][3] - mn1);
                ls0 += p0 + p1; ls1 += p2 + p3;
                Pw[prow0 + nt * 4 + t] = packh2(p0, p1);
                Pw[prow1 + nt * 4 + t] = packh2(p2, p3);
                #pragma unroll
                for (int c = 0; c < 4; c++)
                    oacc[mg][nt][c] *= (c < 2) ? sc0 : sc1;
            }
            ls0 += __shfl_xor_sync(0xFFFFFFFFu, ls0, 1);
            ls0 += __shfl_xor_sync(0xFFFFFFFFu, ls0, 2);
            ls1 += __shfl_xor_sync(0xFFFFFFFFu, ls1, 1);
            ls1 += __shfl_xor_sync(0xFFFFFFFFu, ls1, 2);
            lr[mg][0] = lr[mg][0] * sc0 + ls0;
            lr[mg][1] = lr[mg][1] * sc1 + ls1;
        }
        __syncwarp();

        #pragma unroll
        for (int ks = 0; ks < 4; ks++) {
            uint32_t vf[8][2];
            #pragma unroll
            for (int nt = 0; nt < 8; nt++) {
                vf[nt][0] = Vs[(nt * 8 + g) * KSTH16 + ks * 8 + t];
                vf[nt][1] = Vs[(nt * 8 + g) * KSTH16 + ks * 8 + t + 4];
            }
            #pragma unroll
            for (int mg = 0; mg < 2; mg++) {
                int prow0 = (mg * 64 + warp * 16 + g) * KSTH16;
                int prow1 = prow0 + 8 * KSTH16;
                uint32_t pf[4];
                pf[0] = Pw[prow0 + ks * 8 + t];
                pf[1] = Pw[prow1 + ks * 8 + t];
                pf[2] = Pw[prow0 + ks * 8 + t + 4];
                pf[3] = Pw[prow1 + ks * 8 + t + 4];
                #pragma unroll
                for (int nt = 0; nt < 8; nt++)
                    mma_f16(oacc[mg][nt], pf, vf[nt]);
            }
        }
        __syncthreads();
    }

    #pragma unroll
    for (int mg = 0; mg < 2; mg++) {
        int r0 = rbase + mg * 64, r1 = r0 + 8;
        bool v0 = r0 < S, v1 = r1 < S;
        float inv0 = 1.0f / lr[mg][0], inv1 = 1.0f / lr[mg][1];
        uint32_t* o0 = (uint32_t*)(g_o + (size_t)(b * S + (v0 ? r0 : 0)) * D + h * DH);
        uint32_t* o1 = (uint32_t*)(g_o + (size_t)(b * S + (v1 ? r1 : 0)) * D + h * DH);
        #pragma unroll
        for (int nt = 0; nt < 8; nt++) {
            int wbase = nt * 4 + t;
            if (v0) o0[wbase] = packh2(oacc[mg][nt][0] * inv0, oacc[mg][nt][1] * inv0);
            if (v1) o1[wbase] = packh2(oacc[mg][nt][2] * inv1, oacc[mg][nt][3] * inv1);
        }
    }
}

// ---------------- scatter: feature (smem transpose) + tokens ---------------------
__global__ void __launch_bounds__(256) scatter_feat_kernel(float* __restrict__ out)
{
    __shared__ float ts[32 * 33];
    int pt = blockIdx.x, kt = blockIdx.y, b = blockIdx.z;
    int tid = threadIdx.x;
    int p0 = pt * 32, k0 = kt * 32;
    #pragma unroll
    for (int i = 0; i < 4; i++) {
        int e = i * 256 + tid;
        int p = e >> 5, k = e & 31;
        ts[p * 33 + k] = g_y2[((size_t)(b * S + G + p0 + p)) * D + k0 + k];
    }
    __syncthreads();
    #pragma unroll
    for (int i = 0; i < 4; i++) {
        int e = i * 256 + tid;
        int k = e >> 5, p = e & 31;
        out[((size_t)b * D + k0 + k) * HW + p0 + p] = ts[p * 33 + k];
    }
}

__global__ void __launch_bounds__(256) scatter_tok_kernel(float* __restrict__ out)
{
    const int FEAT = BB * D * HW;
    const int CTX  = BB * D;
    int r = blockIdx.x;
    int b = r / G, s = r % G;
    int tid = threadIdx.x;
    #pragma unroll
    for (int i = 0; i < 3; i++) {
        int k = tid + i * 256;
        float v = g_y2[((size_t)(b * S + s)) * D + k];
        if (s == 0) out[FEAT + b * D + k] = v;
        else        out[FEAT + CTX + ((size_t)b * 4 + (s - 1)) * D + k] = v;
    }
}

// ---------------- host launcher ---------------------------------------------------
extern "C" void kernel_launch(void* const* d_in, const int* in_sizes, int n_in,
                              void* d_out, int out_size)
{
    const float* x    = (const float*)d_in[0];
    const float* ctx  = (const float*)d_in[1];
    const float* regs = (const float*)d_in[2];
    const float* wqkv = (const float*)d_in[3];
    const float* bqkv = (const float*)d_in[4];
    const float* wout = (const float*)d_in[5];
    const float* bout = (const float*)d_in[6];
    const float* ln1s = (const float*)d_in[7];
    const float* ln1b = (const float*)d_in[8];
    const float* ln2s = (const float*)d_in[9];
    const float* ln2b = (const float*)d_in[10];
    const float* w1   = (const float*)d_in[11];
    const float* b1   = (const float*)d_in[12];
    const float* w2   = (const float*)d_in[13];
    const float* b2   = (const float*)d_in[14];
    float* out = (float*)d_out;
    (void)in_sizes; (void)n_in; (void)out_size;

    void *xwt16, *o, *z16, *h16;
    void *wqkv16, *wout16, *w116, *w216;
    float *xwt, *y, *y2;
    cudaGetSymbolAddress((void**)&xwt,    g_xwt);
    cudaGetSymbolAddress(&xwt16,  g_xwt16);
    cudaGetSymbolAddress(&o,      g_o);
    cudaGetSymbolAddress((void**)&y,      g_y);
    cudaGetSymbolAddress(&z16,    g_z16);
    cudaGetSymbolAddress(&h16,    g_h16);
    cudaGetSymbolAddress((void**)&y2,     g_y2);
    cudaGetSymbolAddress(&wqkv16, g_wqkv16);
    cudaGetSymbolAddress(&wout16, g_wout16);
    cudaGetSymbolAddress(&w116,   g_w116);
    cudaGetSymbolAddress(&w216,   g_w216);

    cudaFuncSetAttribute(gemm_f16<false, false, 3>,
        cudaFuncAttributeMaxDynamicSharedMemorySize, GEMMH_SMEM);
    cudaFuncSetAttribute(gemm_f16<false, true, 0>,
        cudaFuncAttributeMaxDynamicSharedMemorySize, GEMMH_SMEM);
    cudaFuncSetAttribute(gemm_f16<true, false, 2>,
        cudaFuncAttributeMaxDynamicSharedMemorySize, GEMMH_SMEM);
    cudaFuncSetAttribute(attn_f16_kernel,
        cudaFuncAttributeMaxDynamicSharedMemorySize, ATTN16_SMEM);
    cudaFuncSetAttribute(build_feat_kernel,
        cudaFuncAttributeMaxDynamicSharedMemorySize, BUILD_SMEM);

    const int M = M_TOT;
    const int MG = (M + 127) / 128;            // 65

    convert_weights_kernel<<<(4 * D * D / 2 + 255) / 256, 256>>>(wqkv, wout, w1, w2);

    build_feat_kernel<<<dim3(HW / 32, BB), 256, BUILD_SMEM>>>(x, ln1s, ln1b);
    build_tok_kernel<<<BB * G, 256>>>(ctx, regs, ln1s, ln1b);

    gemm_f16<false, false, 3><<<dim3(3 * D / 128, MG), 256, GEMMH_SMEM>>>(
        (const uint32_t*)xwt16, (const uint32_t*)wqkv16, bqkv, nullptr,
        nullptr, M, 3 * D, D);

    attn_f16_kernel<<<dim3((S + 127) / 128, NH, BB), 128, ATTN16_SMEM>>>();

    gemm_f16<false, true, 0><<<dim3(D / 128, MG), 256, GEMMH_SMEM>>>(
        (const uint32_t*)o, (const uint32_t*)wout16, bout, xwt,
        y, M, D, D);

    ln_kernel<<<M, 256>>>(y, ln2s, ln2b, (__half*)z16);

    gemm_f16<true, false, 2><<<dim3(4 * D / 128, MG), 256, GEMMH_SMEM>>>(
        (const uint32_t*)z16, (const uint32_t*)w116, b1, nullptr,
        h16, M, 4 * D, D);

    gemm_f16<false, true, 0><<<dim3(D / 128, MG), 256, GEMMH_SMEM>>>(
        (const uint32_t*)h16, (const uint32_t*)w216, b2, y,
        y2, M, D, 4 * D);

    scatter_feat_kernel<<<dim3(HW / 32, D / 32, BB), 256>>>(out);
    scatter_tok_kernel<<<BB * G, 256>>>(out);
}